// round 4
// baseline (speedup 1.0000x reference)
#include <cuda_runtime.h>
#include <cstdint>

// Symmetric one-pass Chamfer: d(i,j) computed once, row-mins (gt->gen) and
// col-mins (gen->gt) extracted simultaneously.
//
// Tiling: block = 64 rows (gt) x 512 cols (gen); 256 threads.
//   thread = 8 rows (4 packed f32x2 query-pairs, registers)
//            x 16 cols (lane-interleaved, splatted in smem).
// Grid = 32 col-blocks x 256 row-blocks = 8192 blocks.

#define N_PTS   16384
#define NB_COL  32          // 16384 / 512
#define NB_ROW  256         // 16384 / 64
#define TPB     256

#define RED_BLOCKS 144      // 128 col-reduce blocks + 16 row-reduce blocks

typedef unsigned long long u64;

// Partial mins, every slot written every run (no init needed).
__device__ float g_rowpart[NB_COL][N_PTS];   // [col-block][row]  : 2 MB
__device__ float g_colpart[NB_ROW][N_PTS];   // [row-block][col]  : 16 MB
__device__ float g_partial[RED_BLOCKS];

// ---------------- f32x2 helpers ----------------
__device__ __forceinline__ u64 pack2(float a, float b) {
    u64 r;
    asm("mov.b64 %0, {%1, %2};" : "=l"(r) : "f"(a), "f"(b));
    return r;
}
__device__ __forceinline__ u64 fma2(u64 a, u64 b, u64 c) {
    u64 d;
    asm("fma.rn.f32x2 %0, %1, %2, %3;" : "=l"(d) : "l"(a), "l"(b), "l"(c));
    return d;
}
__device__ __forceinline__ u64 add2(u64 a, u64 b) {
    u64 d;
    asm("add.rn.f32x2 %0, %1, %2;" : "=l"(d) : "l"(a), "l"(b));
    return d;
}
__device__ __forceinline__ void unpack2(u64 v, float& lo, float& hi) {
    asm("mov.b64 {%0, %1}, %2;" : "=f"(lo), "=f"(hi) : "l"(v));
}

// ---------------- Kernel 1: main symmetric pairwise min ----------------
__global__ __launch_bounds__(TPB, 2) void chamfer_sym_kernel(
    const float* __restrict__ gt, const float* __restrict__ gen) {

    // Splatted col data: 512 cols x 4 dims x 8 B = 16 KB
    __shared__ u64 sCX[512], sCY[512], sCZ[512], sCB[512];
    __shared__ float sRraw[192];                 // 64 row points x 3
    __shared__ float srow[64][33];               // padded: conflict-free
    __shared__ float scol[512][9];               // padded: conflict-free

    const int tid = threadIdx.x;
    const int tc  = tid & 31;    // lane = col group
    const int tr  = tid >> 5;    // warp = row group (0..7)
    const int bx  = blockIdx.x;  // col block (gen)
    const int by  = blockIdx.y;  // row block (gt)

    // ---- stage rows raw (gt): 64 points ----
    if (tid < 192) sRraw[tid] = gt[by * 192 + tid];

    // ---- stage cols (gen): compute -2*coord splat + |b|^2 splat ----
    {
#pragma unroll
        for (int u = 0; u < 2; u++) {
            int jl = 2 * tid + u;                       // local col 0..511
            int g  = (bx * 512 + jl) * 3;
            float x = gen[g + 0];
            float y = gen[g + 1];
            float z = gen[g + 2];
            float cb = x * x + y * y + z * z;
            sCX[jl] = pack2(-2.0f * x, -2.0f * x);
            sCY[jl] = pack2(-2.0f * y, -2.0f * y);
            sCZ[jl] = pack2(-2.0f * z, -2.0f * z);
            sCB[jl] = pack2(cb, cb);
        }
    }
    __syncthreads();

    // ---- load this thread's 8 rows as 4 packed pairs ----
    u64 rx2[4], ry2[4], rz2[4], rca2[4];
#pragma unroll
    for (int p = 0; p < 4; p++) {
        int r0 = tr * 8 + 2 * p;
        float x0 = sRraw[r0 * 3 + 0], y0 = sRraw[r0 * 3 + 1], z0 = sRraw[r0 * 3 + 2];
        float x1 = sRraw[r0 * 3 + 3], y1 = sRraw[r0 * 3 + 4], z1 = sRraw[r0 * 3 + 5];
        float ca0 = x0 * x0 + y0 * y0 + z0 * z0;
        float ca1 = x1 * x1 + y1 * y1 + z1 * z1;
        rx2[p]  = pack2(x0, x1);
        ry2[p]  = pack2(y0, y1);
        rz2[p]  = pack2(z0, z1);
        rca2[p] = pack2(ca0, ca1);
    }

    float rowm[8], colm[16];
#pragma unroll
    for (int k = 0; k < 8; k++)  rowm[k] = 3.4e38f;
#pragma unroll
    for (int c = 0; c < 16; c++) colm[c] = 3.4e38f;

    // ---- main loop: 16 cols x 4 packed row-pairs = 128 pairs/thread ----
#pragma unroll
    for (int c = 0; c < 16; c++) {
        const int ci = tc + 32 * c;
        u64 cx2 = sCX[ci];
        u64 cy2 = sCY[ci];
        u64 cz2 = sCZ[ci];
        u64 cb2 = sCB[ci];
#pragma unroll
        for (int p = 0; p < 4; p++) {
            u64 acc = fma2(rz2[p], cz2, cb2);
            acc = fma2(ry2[p], cy2, acc);
            acc = fma2(rx2[p], cx2, acc);
            u64 d2 = add2(acc, rca2[p]);          // full d for both lanes (2 rows)
            float lo, hi;
            unpack2(d2, lo, hi);
            rowm[2 * p]     = fminf(rowm[2 * p], lo);
            rowm[2 * p + 1] = fminf(rowm[2 * p + 1], hi);
            colm[c] = fminf(colm[c], fminf(lo, hi));
        }
    }

    // ---- block-level partial reductions ----
#pragma unroll
    for (int k = 0; k < 8; k++)  srow[tr * 8 + k][tc] = rowm[k];
#pragma unroll
    for (int c = 0; c < 16; c++) scol[tc + 32 * c][tr] = colm[c];
    __syncthreads();

    if (tid < 64) {
        float m = srow[tid][0];
#pragma unroll
        for (int q = 1; q < 32; q++) m = fminf(m, srow[tid][q]);
        g_rowpart[bx][by * 64 + tid] = m;
    }
#pragma unroll
    for (int u = 0; u < 2; u++) {
        int col = tid + u * 256;
        float m = scol[col][0];
#pragma unroll
        for (int i = 1; i < 8; i++) m = fminf(m, scol[col][i]);
        g_colpart[by][bx * 512 + col] = m;
    }
}

// ---------------- Kernel 2: global min-reduce + block sums ----------------
// Blocks 0..127: col reduce (256 partials/col; warp = 4 cols x 8 chunks of 32).
// Blocks 128..143: row reduce (32 partials/row; 1 row/thread).
__global__ __launch_bounds__(1024) void reduce_sym_kernel() {
    const int tid = threadIdx.x;
    const int bx  = blockIdx.x;
    float v;

    if (bx < 128) {
        int w    = bx * 32 + (tid >> 5);      // global warp 0..4095
        int lane = tid & 31;
        int j    = w * 4 + (lane & 3);        // col 0..16383
        int k    = lane >> 2;                 // chunk 0..7
        float m = 3.4e38f;
#pragma unroll
        for (int p = 0; p < 32; p++)
            m = fminf(m, g_colpart[(k << 5) | p][j]);
        m = fminf(m, __shfl_xor_sync(0xFFFFFFFFu, m, 4));
        m = fminf(m, __shfl_xor_sync(0xFFFFFFFFu, m, 8));
        m = fminf(m, __shfl_xor_sync(0xFFFFFFFFu, m, 16));
        v = (k == 0) ? m : 0.0f;              // one contribution per col
    } else {
        int row = (bx - 128) * 1024 + tid;    // 0..16383
        float m = 3.4e38f;
#pragma unroll
        for (int p = 0; p < 32; p++)
            m = fminf(m, g_rowpart[p][row]);
        v = m;
    }

    // block sum
    __shared__ float ssum[32];
#pragma unroll
    for (int off = 16; off > 0; off >>= 1)
        v += __shfl_xor_sync(0xFFFFFFFFu, v, off);
    int lane = tid & 31;
    int wid  = tid >> 5;
    if (lane == 0) ssum[wid] = v;
    __syncthreads();
    if (wid == 0) {
        float w2 = (lane < 32) ? ssum[lane] : 0.0f;
#pragma unroll
        for (int off = 16; off > 0; off >>= 1)
            w2 += __shfl_xor_sync(0xFFFFFFFFu, w2, off);
        if (lane == 0) g_partial[bx] = w2;
    }
}

// ---------------- Kernel 3: final scalar ----------------
__global__ void final_kernel(float* __restrict__ out) {
    const int tid = threadIdx.x;   // 256 threads
    float v = (tid < RED_BLOCKS) ? g_partial[tid] : 0.0f;
    __shared__ float ssum[8];
#pragma unroll
    for (int off = 16; off > 0; off >>= 1)
        v += __shfl_xor_sync(0xFFFFFFFFu, v, off);
    int lane = tid & 31;
    int wid  = tid >> 5;
    if (lane == 0) ssum[wid] = v;
    __syncthreads();
    if (wid == 0) {
        float w = (lane < 8) ? ssum[lane] : 0.0f;
#pragma unroll
        for (int off = 16; off > 0; off >>= 1)
            w += __shfl_xor_sync(0xFFFFFFFFu, w, off);
        if (lane == 0) out[0] = w * (1.0f / (float)N_PTS);
    }
}

// ---------------- launch ----------------
extern "C" void kernel_launch(void* const* d_in, const int* in_sizes, int n_in,
                              void* d_out, int out_size) {
    const float* gt  = (const float*)d_in[0];
    const float* gen = (const float*)d_in[1];
    float* out = (float*)d_out;

    dim3 grid(NB_COL, NB_ROW);
    chamfer_sym_kernel<<<grid, TPB>>>(gt, gen);
    reduce_sym_kernel<<<RED_BLOCKS, 1024>>>();
    final_kernel<<<1, 256>>>(out);
}